// round 12
// baseline (speedup 1.0000x reference)
#include <cuda_runtime.h>
#include <cstdint>

#define FULLMASK 0xffffffffu

constexpr int B_ = 64, T_ = 512, D_ = 768, K_ = 21;
constexpr int M_ = B_ * T_;          // 32768 rows
constexpr int LOGN = M_ * K_;        // 688128 logits

// -------- device scratch (no allocation allowed) --------
__device__ float g_diff[B_];
__device__ float g_msum[B_];
__device__ float g_logits[LOGN];     // fallback only

// -------- packed fp32x2 FMA helpers (Blackwell dual-fp32 pipe) --------
__device__ __forceinline__ void ffma2(unsigned long long &acc,
                                      unsigned long long a,
                                      unsigned long long b) {
    asm("fma.rn.f32x2 %0, %1, %2, %0;" : "+l"(acc) : "l"(a), "l"(b));
}
__device__ __forceinline__ float2 unpack2(unsigned long long v) {
    float2 f;
    asm("mov.b64 {%0, %1}, %2;" : "=f"(f.x), "=f"(f.y) : "l"(v));
    return f;
}

// ============================================================
// Kernel 1: logits[r][k] = sum_d V[r][d] * W[k][d] + bias[k]
// thread-per-row, W broadcast from shared, V staged in shared.
// ============================================================
constexpr int ROWS_PB = 128;
constexpr int DC = 64;
constexpr int VS_STRIDE = DC + 4;    // 68 floats: float4-aligned, conflict-min

__global__ void __launch_bounds__(128, 2)
gemm_kernel(const float* __restrict__ V, const float* __restrict__ W,
            const float* __restrict__ bias, float* __restrict__ out_logits,
            int use_scratch)
{
    float* L = use_scratch ? g_logits : out_logits;
    extern __shared__ float sm[];
    float* Ws = sm;                       // K_*D_ = 16128 floats
    float* Vs = sm + K_ * D_;             // 128 * 68 floats

    const int tid = threadIdx.x;
    // load W (all blocks; it's hot in L2)
    for (int i = tid; i < (K_ * D_) / 4; i += 128)
        ((float4*)Ws)[i] = ((const float4*)W)[i];

    const int row0 = blockIdx.x * ROWS_PB;

    unsigned long long acc[K_];
#pragma unroll
    for (int k = 0; k < K_; ++k) acc[k] = 0ull;

    const float* vrow_s = Vs + tid * VS_STRIDE;

    for (int dc = 0; dc < D_ / DC; ++dc) {
        __syncthreads();
        // stage V chunk: 128 rows x 64 floats, coalesced
#pragma unroll
        for (int it = 0; it < 16; ++it) {
            int idx = it * 128 + tid;      // float4 index 0..2047
            int r = idx >> 4;
            int c = idx & 15;
            float4 v = *(const float4*)(V + (size_t)(row0 + r) * D_ + dc * DC + c * 4);
            *(float4*)(Vs + r * VS_STRIDE + c * 4) = v;
        }
        __syncthreads();

        const float* wc = Ws + dc * DC;
#pragma unroll
        for (int sub = 0; sub < 4; ++sub) {
            ulonglong2 va = *(const ulonglong2*)(vrow_s + sub * 16);
            ulonglong2 vb = *(const ulonglong2*)(vrow_s + sub * 16 + 4);
            ulonglong2 vc = *(const ulonglong2*)(vrow_s + sub * 16 + 8);
            ulonglong2 vd = *(const ulonglong2*)(vrow_s + sub * 16 + 12);
#pragma unroll
            for (int k = 0; k < K_; ++k) {
                const float* wp = wc + k * D_ + sub * 16;   // broadcast LDS
                ulonglong2 wa  = *(const ulonglong2*)(wp);
                ulonglong2 wb  = *(const ulonglong2*)(wp + 4);
                ulonglong2 wcc = *(const ulonglong2*)(wp + 8);
                ulonglong2 wd  = *(const ulonglong2*)(wp + 12);
                ffma2(acc[k], va.x, wa.x);  ffma2(acc[k], va.y, wa.y);
                ffma2(acc[k], vb.x, wb.x);  ffma2(acc[k], vb.y, wb.y);
                ffma2(acc[k], vc.x, wcc.x); ffma2(acc[k], vc.y, wcc.y);
                ffma2(acc[k], vd.x, wd.x);  ffma2(acc[k], vd.y, wd.y);
            }
        }
    }

    const size_t orow = (size_t)(row0 + tid) * K_;
#pragma unroll
    for (int k = 0; k < K_; ++k) {
        float2 f = unpack2(acc[k]);
        L[orow + k] = f.x + f.y + __ldg(bias + k);
    }
}

// ============================================================
// Kernel 2: per-sequence CRF. warp0 = scaled forward algorithm
// (exponential domain), warp1 = gold path score + mask sum.
// ============================================================
__global__ void __launch_bounds__(64, 1)
crf_kernel(const float* __restrict__ out_logits, int use_scratch,
           const int* __restrict__ tags, const int* __restrict__ mask,
           const float* __restrict__ trans, const float* __restrict__ startt,
           const float* __restrict__ endt)
{
    const float* L = use_scratch ? g_logits : out_logits;
    const int b = blockIdx.x;
    const int tid = threadIdx.x;
    const int wid = tid >> 5;
    const int j = tid & 31;

    __shared__ float sE[T_ * K_];   // exp(logits) for this sequence, 43 KB
    __shared__ float sM[T_];        // mask as float
    __shared__ float s_res[3];      // logZ, score, msum

    const float* Lb = L + (size_t)b * T_ * K_;

    // stage exp(emissions) + mask into shared (both warps)
#pragma unroll 4
    for (int i = tid; i < T_ * K_; i += 64)
        sE[i] = __expf(Lb[i]);
    for (int i = tid; i < T_; i += 64)
        sM[i] = (float)mask[b * T_ + i];
    __syncthreads();

    if (wid == 0) {
        // ---- scaled forward algorithm (linear domain, periodic renorm) ----
        float Ec[K_];
#pragma unroll
        for (int i = 0; i < K_; ++i)
            Ec[i] = (j < K_) ? __expf(trans[i * K_ + j]) : 0.f;

        // alpha0 = start + logits[0]  ->  p = exp(start)*exp(logit0)
        float p = (j < K_) ? __expf(startt[j]) * sE[j] : 0.f;
        float lz = 0.f;

        for (int t = 1; t < T_; ++t) {
            float e  = (j < K_) ? sE[t * K_ + j] : 0.f;
            float mt = sM[t];
            float s0 = 0.f, s1 = 0.f, s2 = 0.f;
#pragma unroll
            for (int i = 0; i < K_; i += 3) {
                s0 = fmaf(__shfl_sync(FULLMASK, p, i),     Ec[i],     s0);
                s1 = fmaf(__shfl_sync(FULLMASK, p, i + 1), Ec[i + 1], s1);
                s2 = fmaf(__shfl_sync(FULLMASK, p, i + 2), Ec[i + 2], s2);
            }
            float pn = (s0 + s1 + s2) * e;
            p = (mt != 0.f) ? pn : p;          // masked step keeps alpha
            if ((t & 7) == 7) {                // renormalize every 8 steps
                float c = p;
#pragma unroll
                for (int o = 16; o; o >>= 1) c += __shfl_xor_sync(FULLMASK, c, o);
                p *= (1.0f / c);
                lz += __logf(c);
            }
        }
        float w = (j < K_) ? p * __expf(endt[j]) : 0.f;
#pragma unroll
        for (int o = 16; o; o >>= 1) w += __shfl_xor_sync(FULLMASK, w, o);
        if (j == 0) s_res[0] = lz + __logf(w);
    } else {
        // ---- gold (numerator) score + mask sum ----
        float acc = 0.f, msum = 0.f;
        for (int t = j; t < T_; t += 32) {
            float mc = sM[t];
            msum += mc;
            if (t < T_ - 1) {
                int cur = tags[b * T_ + t];
                int nxt = tags[b * T_ + t + 1];
                float mn = sM[t + 1];
                acc += trans[cur * K_ + nxt] * mn + Lb[(size_t)t * K_ + cur] * mc;
            }
        }
#pragma unroll
        for (int o = 16; o; o >>= 1) {
            acc  += __shfl_xor_sync(FULLMASK, acc,  o);
            msum += __shfl_xor_sync(FULLMASK, msum, o);
        }
        if (j == 0) {
            int li = (int)msum - 1;                 // index of last valid step
            int ltag = tags[b * T_ + li];
            acc += startt[tags[b * T_]] + endt[ltag]
                 + Lb[(size_t)(T_ - 1) * K_ + ltag] * sM[T_ - 1];
            s_res[1] = acc;
            s_res[2] = msum;
        }
    }
    __syncthreads();
    if (tid == 0) {
        g_diff[b] = s_res[1] - s_res[0];
        g_msum[b] = s_res[2];
    }
}

// ============================================================
// Kernel 3: loss = -(sum_b diff_b) / (sum_b msum_b)
// ============================================================
__global__ void finalize_kernel(float* __restrict__ out)
{
    int l = threadIdx.x;
    float d = g_diff[l] + g_diff[l + 32];
    float m = g_msum[l] + g_msum[l + 32];
#pragma unroll
    for (int o = 16; o; o >>= 1) {
        d += __shfl_xor_sync(FULLMASK, d, o);
        m += __shfl_xor_sync(FULLMASK, m, o);
    }
    if (l == 0) out[0] = -d / m;
}

// ============================================================
// launch
// ============================================================
extern "C" void kernel_launch(void* const* d_in, const int* in_sizes, int n_in,
                              void* d_out, int out_size)
{
    const float* V      = (const float*)d_in[0];   // vectors [64,512,768]
    const int*   tags   = (const int*)  d_in[1];   // targets [64,512]
    const int*   mask   = (const int*)  d_in[2];   // mask [64,512]
    const float* W      = (const float*)d_in[3];   // W [21,768]
    const float* bias   = (const float*)d_in[4];   // b [21]
    const float* trans  = (const float*)d_in[5];   // transitions [21,21]
    const float* startt = (const float*)d_in[6];   // start_trans [21]
    const float* endt   = (const float*)d_in[7];   // end_trans [21]
    float* out = (float*)d_out;

    // Output layout: tuple (loss, logits) flattened -> loss at [0], logits after.
    int off = out_size - LOGN;
    int use_scratch = 0;
    float* Lptr = nullptr;
    if (off >= 0) {
        Lptr = out + off;
    } else {
        use_scratch = 1;           // no room for logits in d_out (defensive)
    }

    size_t smem = (size_t)(K_ * D_ + ROWS_PB * VS_STRIDE) * sizeof(float);
    cudaFuncSetAttribute(gemm_kernel, cudaFuncAttributeMaxDynamicSharedMemorySize,
                         (int)smem);

    gemm_kernel<<<M_ / ROWS_PB, 128, smem>>>(V, W, bias, Lptr, use_scratch);
    crf_kernel<<<B_, 64>>>(Lptr, use_scratch, tags, mask, trans, startt, endt);
    if (off >= 1) finalize_kernel<<<1, 32>>>(out);
}

// round 13
// speedup vs baseline: 1.1597x; 1.1597x over previous
#include <cuda_runtime.h>
#include <cstdint>

#define FULLMASK 0xffffffffu

constexpr int B_ = 64, T_ = 512, D_ = 768, K_ = 21;
constexpr int M_ = B_ * T_;          // 32768 rows
constexpr int LOGN = M_ * K_;        // 688128 logits

// -------- device scratch (no allocation allowed) --------
__device__ float g_diff[B_];
__device__ float g_msum[B_];
__device__ float g_logits[LOGN];     // fallback only

// -------- packed fp32x2 FMA helpers (Blackwell dual-fp32 pipe) --------
__device__ __forceinline__ void ffma2(unsigned long long &acc,
                                      unsigned long long a,
                                      unsigned long long b) {
    asm("fma.rn.f32x2 %0, %1, %2, %0;" : "+l"(acc) : "l"(a), "l"(b));
}
__device__ __forceinline__ float2 unpack2(unsigned long long v) {
    float2 f;
    asm("mov.b64 {%0, %1}, %2;" : "=f"(f.x), "=f"(f.y) : "l"(v));
    return f;
}

// ============================================================
// Kernel 1: logits[r][k] = sum_d V[r][d] * W[k][d] + bias[k]
// thread-per-row. W broadcast from shared. V chunks software-
// pipelined through registers into shared. Inner loop ordered
// k-innermost so consecutive FFMA2 hit independent accumulators.
// ============================================================
constexpr int ROWS_PB = 128;
constexpr int DC = 64;
constexpr int VS_STRIDE = DC + 4;    // 68 floats: 16B-aligned, conflict-free

__global__ void __launch_bounds__(128, 2)
gemm_kernel(const float* __restrict__ V, const float* __restrict__ W,
            const float* __restrict__ bias, float* __restrict__ out_logits,
            int use_scratch)
{
    float* L = use_scratch ? g_logits : out_logits;
    extern __shared__ float sm[];
    float* Ws = sm;                       // K_*D_ = 16128 floats (63KB)
    float* Vs = sm + K_ * D_;             // 128 * 68 floats (34.8KB)

    const int tid = threadIdx.x;
    // load W into shared (hot in L2 across blocks)
    for (int i = tid; i < (K_ * D_) / 4; i += 128)
        ((float4*)Ws)[i] = ((const float4*)W)[i];

    const int row0 = blockIdx.x * ROWS_PB;

    unsigned long long acc[K_];
#pragma unroll
    for (int k = 0; k < K_; ++k) acc[k] = 0ull;

    const float* vrow_s = Vs + tid * VS_STRIDE;

    // prefetch chunk 0 into registers
    float4 nxt[16];
#pragma unroll
    for (int it = 0; it < 16; ++it) {
        int idx = it * 128 + tid;          // float4 index within 128x64 chunk
        int r = idx >> 4;
        int c = idx & 15;
        nxt[it] = *(const float4*)(V + (size_t)(row0 + r) * D_ + c * 4);
    }

    for (int dc = 0; dc < D_ / DC; ++dc) {
        __syncthreads();                   // prior chunk's compute done
#pragma unroll
        for (int it = 0; it < 16; ++it) {
            int idx = it * 128 + tid;
            int r = idx >> 4;
            int c = idx & 15;
            *(float4*)(Vs + r * VS_STRIDE + c * 4) = nxt[it];
        }
        __syncthreads();

        // prefetch next chunk (LDGs issue before compute, hide DRAM latency)
        if (dc + 1 < D_ / DC) {
#pragma unroll
            for (int it = 0; it < 16; ++it) {
                int idx = it * 128 + tid;
                int r = idx >> 4;
                int c = idx & 15;
                nxt[it] = *(const float4*)(V + (size_t)(row0 + r) * D_
                                             + (dc + 1) * DC + c * 4);
            }
        }

        const float* wc = Ws + dc * DC;
#pragma unroll
        for (int q = 0; q < 16; ++q) {     // q = 4 floats of this row
            ulonglong2 v = *(const ulonglong2*)(vrow_s + q * 4);
#pragma unroll
            for (int k = 0; k < K_; ++k) { // 21 independent acc updates
                ulonglong2 w = *(const ulonglong2*)(wc + k * D_ + q * 4);
                ffma2(acc[k], v.x, w.x);
                ffma2(acc[k], v.y, w.y);
            }
        }
    }

    const size_t orow = (size_t)(row0 + tid) * K_;
#pragma unroll
    for (int k = 0; k < K_; ++k) {
        float2 f = unpack2(acc[k]);
        L[orow + k] = f.x + f.y + __ldg(bias + k);
    }
}

// ============================================================
// Kernel 2: per-sequence CRF.
//  staging: emissions pre-scaled by per-step max c_t (sE = exp(l - c_t))
//  warp0: scaled forward algorithm, renorm every 16 steps (safe: e' <= 1)
//  warp1: gold path score + mask sum + sum of c_t corrections
// ============================================================
__global__ void __launch_bounds__(64, 1)
crf_kernel(const float* __restrict__ out_logits, int use_scratch,
           const int* __restrict__ tags, const int* __restrict__ mask,
           const float* __restrict__ trans, const float* __restrict__ startt,
           const float* __restrict__ endt)
{
    const float* L = use_scratch ? g_logits : out_logits;
    const int b = blockIdx.x;
    const int tid = threadIdx.x;
    const int wid = tid >> 5;
    const int j = tid & 31;

    __shared__ float sE[T_ * K_ + 32];  // padded: lanes 21..31 read past row end
    __shared__ float sC[T_];            // per-step max (scale correction)
    __shared__ float sM[T_];            // mask as float
    __shared__ float s_res[4];          // logZ_part, score, msum, csum

    const float* Lb = L + (size_t)b * T_ * K_;

    // ---- staging: each thread handles 8 timesteps ----
#pragma unroll
    for (int u = 0; u < 8; ++u) {
        int t = u * 64 + tid;
        const float* lp = Lb + (size_t)t * K_;
        float v[K_];
        float c = lp[0];
        v[0] = c;
#pragma unroll
        for (int k = 1; k < K_; ++k) { v[k] = lp[k]; c = fmaxf(c, v[k]); }
        sC[t] = c;
#pragma unroll
        for (int k = 0; k < K_; ++k) sE[t * K_ + k] = __expf(v[k] - c);
    }
    for (int i = tid; i < T_; i += 64)
        sM[i] = (float)mask[b * T_ + i];
    __syncthreads();

    if (wid == 0) {
        // ---- scaled forward (linear domain) ----
        float Ec[K_];
#pragma unroll
        for (int i = 0; i < K_; ++i)
            Ec[i] = (j < K_) ? __expf(trans[i * K_ + j]) : 0.f;

        float p = (j < K_) ? __expf(startt[j]) * sE[j] : 0.f;
        float lz = 0.f;
        float e_next = sE[K_ + j];

        for (int t = 1; t < T_; ++t) {
            float e = e_next;
            e_next = sE[(t + 1) * K_ + j];      // padded; garbage at t=511 unused
            float mt = sM[t];
            float s[7];
#pragma unroll
            for (int w = 0; w < 7; ++w) {
                int i = w * 3;
                float a = fmaf(__shfl_sync(FULLMASK, p, i),     Ec[i],     0.f);
                a = fmaf(__shfl_sync(FULLMASK, p, i + 1), Ec[i + 1], a);
                s[w] = fmaf(__shfl_sync(FULLMASK, p, i + 2), Ec[i + 2], a);
            }
            float pn = (((s[0] + s[1]) + (s[2] + s[3])) +
                        ((s[4] + s[5]) + s[6])) * e;
            p = (mt != 0.f) ? pn : p;           // masked step keeps alpha
            if ((t & 15) == 15) {               // renorm every 16 (overflow-safe)
                float c = p;
#pragma unroll
                for (int o = 16; o; o >>= 1) c += __shfl_xor_sync(FULLMASK, c, o);
                p *= (1.0f / c);
                lz += __logf(c);
            }
        }
        float w = (j < K_) ? p * __expf(endt[j]) : 0.f;
#pragma unroll
        for (int o = 16; o; o >>= 1) w += __shfl_xor_sync(FULLMASK, w, o);
        if (j == 0) s_res[0] = lz + __logf(w);
    } else {
        // ---- gold (numerator) score + mask sum + scale-correction sum ----
        float acc = 0.f, msum = 0.f, csum = 0.f;
        for (int t = j; t < T_; t += 32) {
            float mc = sM[t];
            msum += mc;
            csum += (t == 0) ? sC[0] : sC[t] * mc;
            if (t < T_ - 1) {
                int cur = tags[b * T_ + t];
                int nxt = tags[b * T_ + t + 1];
                acc += trans[cur * K_ + nxt] * sM[t + 1]
                     + Lb[(size_t)t * K_ + cur] * mc;
            }
        }
#pragma unroll
        for (int o = 16; o; o >>= 1) {
            acc  += __shfl_xor_sync(FULLMASK, acc,  o);
            msum += __shfl_xor_sync(FULLMASK, msum, o);
            csum += __shfl_xor_sync(FULLMASK, csum, o);
        }
        if (j == 0) {
            int li = (int)msum - 1;             // last valid index
            int ltag = tags[b * T_ + li];
            acc += startt[tags[b * T_]] + endt[ltag]
                 + Lb[(size_t)(T_ - 1) * K_ + ltag] * sM[T_ - 1];
            s_res[1] = acc;
            s_res[2] = msum;
            s_res[3] = csum;
        }
    }
    __syncthreads();
    if (tid == 0) {
        g_diff[b] = s_res[1] - (s_res[0] + s_res[3]);
        g_msum[b] = s_res[2];
    }
}

// ============================================================
// Kernel 3: loss = -(sum_b diff_b) / (sum_b msum_b)
// ============================================================
__global__ void finalize_kernel(float* __restrict__ out)
{
    int l = threadIdx.x;
    float d = g_diff[l] + g_diff[l + 32];
    float m = g_msum[l] + g_msum[l + 32];
#pragma unroll
    for (int o = 16; o; o >>= 1) {
        d += __shfl_xor_sync(FULLMASK, d, o);
        m += __shfl_xor_sync(FULLMASK, m, o);
    }
    if (l == 0) out[0] = -d / m;
}

// ============================================================
// launch
// ============================================================
extern "C" void kernel_launch(void* const* d_in, const int* in_sizes, int n_in,
                              void* d_out, int out_size)
{
    const float* V      = (const float*)d_in[0];   // vectors [64,512,768]
    const int*   tags   = (const int*)  d_in[1];   // targets [64,512]
    const int*   mask   = (const int*)  d_in[2];   // mask [64,512]
    const float* W      = (const float*)d_in[3];   // W [21,768]
    const float* bias   = (const float*)d_in[4];   // b [21]
    const float* trans  = (const float*)d_in[5];   // transitions [21,21]
    const float* startt = (const float*)d_in[6];   // start_trans [21]
    const float* endt   = (const float*)d_in[7];   // end_trans [21]
    float* out = (float*)d_out;

    // Output layout: (loss, logits) flattened -> loss at [0], logits after.
    int off = out_size - LOGN;
    int use_scratch = 0;
    float* Lptr = nullptr;
    if (off >= 0) {
        Lptr = out + off;
    } else {
        use_scratch = 1;           // defensive fallback
    }

    size_t smem = (size_t)(K_ * D_ + ROWS_PB * VS_STRIDE) * sizeof(float);
    cudaFuncSetAttribute(gemm_kernel, cudaFuncAttributeMaxDynamicSharedMemorySize,
                         (int)smem);

    gemm_kernel<<<M_ / ROWS_PB, 128, smem>>>(V, W, bias, Lptr, use_scratch);
    crf_kernel<<<B_, 64>>>(Lptr, use_scratch, tags, mask, trans, startt, endt);
    if (off >= 1) finalize_kernel<<<1, 32>>>(out);
}